// round 3
// baseline (speedup 1.0000x reference)
#include <cuda_runtime.h>
#include <cstddef>

#define NB 4
#define CIN 64
#define NF 256
#define NT 256
#define TCC 64
#define DC 16
#define NY 320          // TCC + NT
#define CF 48           // 3*DC
#define CT 32           // 2*DC
#define CALL 80         // CF + CT
#define ATT_SCALE 0.25f // 1/sqrt(16)
#define ESHIFT 20.0f
#define EPS 1e-5f

// ---------------- scratch (__device__ globals; no runtime allocation) -------
__device__ float g_fqkv [NB*CF*NF*NT];        // [b][c48][f][t]
__device__ float g_fqkvT[NB*NT*CF*NF];        // [b][t][c48][f]
__device__ float g_qt   [NB*DC*NF*NT];        // [b][c][f][t]
__device__ float g_kt   [NB*DC*NF*NY];        // [b][c][f][y]  (y: cache|new)
__device__ float g_fout [NB*DC*NF*NY];        // [b][c][f][y]
__device__ float g_E    [(size_t)NB*NF*NY*NT];// [b][f][y][t]
__device__ float g_Lr   [NB*NY*NT];           // [b][y][t] = 1/L
__device__ float g_tout [NB*DC*NF*NT];        // [b][c][f][t]

// ---------------- fused conv 1x1 + BN + PReLU (fqkv 48ch + tqk 32ch) --------
// Weight smem layout transposed to [c][j] so the inner loop does float4 LDS
// (4 FMA per LDS.128 instead of 1 FMA per scalar LDS).
__global__ void k_convs(const float* __restrict__ inp,
                        const float* __restrict__ wf,
                        const float* __restrict__ gf,
                        const float* __restrict__ bf_,
                        const float* __restrict__ mf,
                        const float* __restrict__ vf,
                        const float* __restrict__ af,
                        const float* __restrict__ wt,
                        const float* __restrict__ gt,
                        const float* __restrict__ bt_,
                        const float* __restrict__ mt,
                        const float* __restrict__ vt,
                        const float* __restrict__ at_)
{
    __shared__ float ws[CIN*CALL];     // 20KB: [c][j], j: 0..47 fqkv, 48..79 tqk
    __shared__ float sc[CALL], sh[CALL], al[CALL];
    int bf = blockIdx.x;
    int b = bf >> 8, f = bf & 255;
    int t = threadIdx.x;
    for (int i = t; i < CF*CIN; i += 256) {
        int j = i / CIN, c = i % CIN;
        ws[c*CALL + j] = wf[i];
    }
    for (int i = t; i < CT*CIN; i += 256) {
        int j = i / CIN, c = i % CIN;
        ws[c*CALL + CF + j] = wt[i];
    }
    if (t < CALL) {
        float gv, bv, mv, vv, av;
        if (t < CF) { gv=gf[t]; bv=bf_[t]; mv=mf[t]; vv=vf[t]; av=af[t]; }
        else { int j=t-CF; gv=gt[j]; bv=bt_[j]; mv=mt[j]; vv=vt[j]; av=at_[j]; }
        float r = rsqrtf(vv + EPS);
        sc[t] = gv * r;
        sh[t] = bv - mv * gv * r;
        al[t] = av;
    }
    __syncthreads();

    float acc[CALL];
    #pragma unroll
    for (int j = 0; j < CALL; j++) acc[j] = 0.f;
    const float* ip = inp + ((size_t)b*CIN*NF + f)*NT + t;
    const float4* ws4 = (const float4*)ws;
    for (int c = 0; c < CIN; c++) {
        float x = ip[(size_t)c*NF*NT];
        #pragma unroll
        for (int j4 = 0; j4 < CALL/4; j4++) {
            float4 w = ws4[c*(CALL/4) + j4];
            acc[4*j4+0] += w.x * x;
            acc[4*j4+1] += w.y * x;
            acc[4*j4+2] += w.z * x;
            acc[4*j4+3] += w.w * x;
        }
    }
    #pragma unroll
    for (int j = 0; j < CALL; j++) {
        float yv = acc[j]*sc[j] + sh[j];
        yv = (yv >= 0.f) ? yv : al[j]*yv;
        if (j < CF)
            g_fqkv[(((size_t)b*CF + j)*NF + f)*NT + t] = yv;
        else if (j < CF + DC)
            g_qt[(((size_t)b*DC + (j-CF))*NF + f)*NT + t] = yv;
        else
            g_kt[(((size_t)b*DC + (j-CF-DC))*NF + f)*NY + TCC + t] = yv;
    }
}

// ---------------- transpose [b][c][f][t] -> [b][t][c][f] --------------------
__global__ void k_transpose()
{
    __shared__ float tile[32][33];
    int bc = blockIdx.z;                 // b*CF + c
    int b = bc / CF, c = bc % CF;
    int f0 = blockIdx.y * 32, t0 = blockIdx.x * 32;
    const float* in = g_fqkv + (size_t)bc*NF*NT;
    for (int i = threadIdx.y; i < 32; i += 8)
        tile[i][threadIdx.x] = in[(size_t)(f0+i)*NT + t0 + threadIdx.x];
    __syncthreads();
    for (int i = threadIdx.y; i < 32; i += 8)
        g_fqkvT[(((size_t)b*NT + t0 + i)*CF + c)*NF + f0 + threadIdx.x]
            = tile[threadIdx.x][i];
}

// ---------------- splice cache into g_kt / g_fout ---------------------------
__global__ void k_cache_in(const float* __restrict__ cache)
{
    int idx = blockIdx.x*256 + threadIdx.x;
    int n = NB*DC*NF*TCC;
    int which = (idx >= n);          // 0: k_cache, 1: v_cache
    int i = which ? idx - n : idx;
    int tc = i % TCC;
    int f  = (i / TCC) % NF;
    int c  = (i / (TCC*NF)) % DC;
    int b  = i / (TCC*NF*DC);
    float val = cache[((((size_t)b*2*DC) + which*DC + c)*NF + f)*TCC + tc];
    float* dst = which ? g_fout : g_kt;
    dst[(((size_t)b*DC + c)*NF + f)*NY + tc] = val;
}

// ---------------- f-attention: per (b,t), softmax over y --------------------
__global__ void k_fattn()
{
    __shared__ float sm[CF*NF];   // q[0:16)|k[16:32)|v[32:48), each [c][f] — 48KB
    int bt = blockIdx.x;
    int b = bt >> 8, t = bt & 255;
    const float* src = g_fqkvT + (size_t)(b*NT + t)*CF*NF;
    for (int i = threadIdx.x; i < CF*NF; i += 256) sm[i] = src[i];
    __syncthreads();

    int f = threadIdx.x;
    float q[DC];
    #pragma unroll
    for (int c = 0; c < DC; c++) q[c] = sm[c*NF + f];
    float o[DC];
    #pragma unroll
    for (int c = 0; c < DC; c++) o[c] = 0.f;
    float l = 0.f;

    const float4* k4 = (const float4*)(sm + DC*NF);
    const float4* v4 = (const float4*)(sm + 2*DC*NF);
    for (int yg = 0; yg < NT/4; yg++) {
        float s0=0.f, s1=0.f, s2=0.f, s3=0.f;
        #pragma unroll
        for (int c = 0; c < DC; c++) {
            float4 kk = k4[c*(NF/4) + yg];
            s0 += q[c]*kk.x; s1 += q[c]*kk.y; s2 += q[c]*kk.z; s3 += q[c]*kk.w;
        }
        float e0 = __expf(s0*ATT_SCALE - ESHIFT);
        float e1 = __expf(s1*ATT_SCALE - ESHIFT);
        float e2 = __expf(s2*ATT_SCALE - ESHIFT);
        float e3 = __expf(s3*ATT_SCALE - ESHIFT);
        l += e0 + e1 + e2 + e3;
        #pragma unroll
        for (int c = 0; c < DC; c++) {
            float4 vv = v4[c*(NF/4) + yg];
            o[c] += e0*vv.x + e1*vv.y + e2*vv.z + e3*vv.w;
        }
    }
    float inv = 1.f / l;
    #pragma unroll
    for (int c = 0; c < DC; c++)
        g_fout[(((size_t)b*DC + c)*NF + f)*NY + TCC + t] = o[c]*inv;
}

// ---------------- t-attention scores: E = exp(s*scale - C) ------------------
__global__ void k_escore()
{
    __shared__ float qs[DC*NT];   // 16KB  [c][t]
    __shared__ float ks[DC*NY];   // 20KB  [c][y]
    int bf = blockIdx.x;
    int b = bf >> 8, f = bf & 255;
    for (int i = threadIdx.x; i < DC*NT; i += 256) {
        int c = i >> 8, t = i & 255;
        qs[i] = g_qt[(((size_t)b*DC + c)*NF + f)*NT + t];
    }
    for (int i = threadIdx.x; i < DC*NY; i += 256) {
        int c = i / NY, y = i - c*NY;
        ks[i] = g_kt[(((size_t)b*DC + c)*NF + f)*NY + y];
    }
    __syncthreads();

    int t = threadIdx.x;
    float q[DC];
    #pragma unroll
    for (int c = 0; c < DC; c++) q[c] = qs[c*NT + t];

    float* Eo = g_E + ((size_t)(b*NF + f)*NY)*NT + t;
    const float4* k4 = (const float4*)ks;
    for (int yg = 0; yg < NY/4; yg++) {
        float s0=0.f, s1=0.f, s2=0.f, s3=0.f;
        #pragma unroll
        for (int c = 0; c < DC; c++) {
            float4 kk = k4[c*(NY/4) + yg];
            s0 += q[c]*kk.x; s1 += q[c]*kk.y; s2 += q[c]*kk.z; s3 += q[c]*kk.w;
        }
        Eo[(size_t)(4*yg+0)*NT] = __expf(s0*ATT_SCALE - ESHIFT);
        Eo[(size_t)(4*yg+1)*NT] = __expf(s1*ATT_SCALE - ESHIFT);
        Eo[(size_t)(4*yg+2)*NT] = __expf(s2*ATT_SCALE - ESHIFT);
        Eo[(size_t)(4*yg+3)*NT] = __expf(s3*ATT_SCALE - ESHIFT);
    }
}

// ---------------- reduce L over f, store reciprocal -------------------------
__global__ void k_lred()
{
    int by = blockIdx.x;
    int b = by / NY, y = by % NY;
    int t = threadIdx.x;
    const float* e = g_E + ((size_t)b*NF*NY + y)*NT + t;
    float a0=0.f, a1=0.f, a2=0.f, a3=0.f;
    const size_t st = (size_t)NY*NT;
    for (int f = 0; f < NF; f += 4) {
        a0 += e[(size_t)(f+0)*st];
        a1 += e[(size_t)(f+1)*st];
        a2 += e[(size_t)(f+2)*st];
        a3 += e[(size_t)(f+3)*st];
    }
    g_Lr[((size_t)b*NY + y)*NT + t] = 1.f / (a0+a1+a2+a3);
}

// ---------------- t_out = sum_y (E*Lr) * f_out ------------------------------
// fo smem layout [y][c] so the inner loop does 4 LDS.128 per y (16 FMA).
__global__ void k_tout()
{
    __shared__ float fo[NY*DC];   // 20KB [y][c]
    int bf = blockIdx.x;
    int b = bf >> 8, f = bf & 255;
    for (int i = threadIdx.x; i < DC*NY; i += 256) {
        int c = i / NY, y = i - c*NY;
        fo[y*DC + c] = g_fout[(((size_t)b*DC + c)*NF + f)*NY + y];
    }
    __syncthreads();

    int t = threadIdx.x;
    float o[DC];
    #pragma unroll
    for (int c = 0; c < DC; c++) o[c] = 0.f;
    const float* Ep = g_E  + (size_t)(b*NF + f)*NY*NT + t;
    const float* Lp = g_Lr + (size_t)b*NY*NT + t;
    const float4* fo4 = (const float4*)fo;
    #pragma unroll 4
    for (int y = 0; y < NY; y++) {
        float p = Ep[(size_t)y*NT] * Lp[(size_t)y*NT];
        #pragma unroll
        for (int c4 = 0; c4 < DC/4; c4++) {
            float4 vv = fo4[y*(DC/4) + c4];
            o[4*c4+0] += p * vv.x;
            o[4*c4+1] += p * vv.y;
            o[4*c4+2] += p * vv.z;
            o[4*c4+3] += p * vv.w;
        }
    }
    #pragma unroll
    for (int c = 0; c < DC; c++)
        g_tout[(((size_t)b*DC + c)*NF + f)*NT + t] = o[c];
}

// ---------------- proj conv + BN + PReLU + residual -------------------------
// ws smem layout [c][oc], float4 over oc.
__global__ void k_proj(const float* __restrict__ inp,
                       const float* __restrict__ w,
                       const float* __restrict__ g,
                       const float* __restrict__ bb,
                       const float* __restrict__ m,
                       const float* __restrict__ v,
                       const float* __restrict__ a,
                       float* __restrict__ out)
{
    __shared__ float ws[DC*CIN];   // [c][oc]
    __shared__ float sc[CIN], sh[CIN], al[CIN];
    int bf = blockIdx.x;
    int b = bf >> 8, f = bf & 255;
    int t = threadIdx.x;
    for (int i = t; i < CIN*DC; i += 256) {
        int oc = i / DC, c = i % DC;
        ws[c*CIN + oc] = w[i];
    }
    if (t < CIN) {
        float r = rsqrtf(v[t] + EPS);
        sc[t] = g[t] * r;
        sh[t] = bb[t] - m[t] * g[t] * r;
        al[t] = a[t];
    }
    __syncthreads();

    float acc[CIN];
    #pragma unroll
    for (int oc = 0; oc < CIN; oc++) acc[oc] = 0.f;
    const float4* ws4 = (const float4*)ws;
    #pragma unroll
    for (int c = 0; c < DC; c++) {
        float x = g_tout[(((size_t)b*DC + c)*NF + f)*NT + t];
        #pragma unroll
        for (int o4 = 0; o4 < CIN/4; o4++) {
            float4 wv = ws4[c*(CIN/4) + o4];
            acc[4*o4+0] += wv.x * x;
            acc[4*o4+1] += wv.y * x;
            acc[4*o4+2] += wv.z * x;
            acc[4*o4+3] += wv.w * x;
        }
    }
    #pragma unroll
    for (int oc = 0; oc < CIN; oc++) {
        float yv = acc[oc]*sc[oc] + sh[oc];
        yv = (yv >= 0.f) ? yv : al[oc]*yv;
        size_t idx = (((size_t)b*CIN + oc)*NF + f)*NT + t;
        out[idx] = yv + inp[idx];
    }
}

// ---------------- write new_cache slice -------------------------------------
__global__ void k_cache_out(float* __restrict__ out)
{
    int idx = blockIdx.x*256 + threadIdx.x;
    const int n = NB * 2*DC * NF * (NY-1);  // 10,452,992
    if (idx >= n) return;
    int i = idx;
    int yy = i % (NY-1); i /= (NY-1);
    int f  = i % NF;     i /= NF;
    int cc = i % (2*DC); i /= (2*DC);
    int b  = i;
    const float* src = (cc < DC) ? g_kt : g_fout;
    int c = (cc < DC) ? cc : cc - DC;
    out[(size_t)NB*CIN*NF*NT + idx] =
        src[(((size_t)b*DC + c)*NF + f)*NY + 1 + yy];
}

// ---------------- launcher --------------------------------------------------
extern "C" void kernel_launch(void* const* d_in, const int* in_sizes, int n_in,
                              void* d_out, int out_size)
{
    const float* inp    = (const float*)d_in[0];
    const float* cache  = (const float*)d_in[1];
    const float* fqkv_w = (const float*)d_in[2];
    const float* fqkv_g = (const float*)d_in[3];
    const float* fqkv_b = (const float*)d_in[4];
    const float* fqkv_m = (const float*)d_in[5];
    const float* fqkv_v = (const float*)d_in[6];
    const float* fqkv_a = (const float*)d_in[7];
    const float* tqk_w  = (const float*)d_in[8];
    const float* tqk_g  = (const float*)d_in[9];
    const float* tqk_b  = (const float*)d_in[10];
    const float* tqk_m  = (const float*)d_in[11];
    const float* tqk_v  = (const float*)d_in[12];
    const float* tqk_a  = (const float*)d_in[13];
    const float* proj_w = (const float*)d_in[14];
    const float* proj_g = (const float*)d_in[15];
    const float* proj_b = (const float*)d_in[16];
    const float* proj_m = (const float*)d_in[17];
    const float* proj_v = (const float*)d_in[18];
    const float* proj_a = (const float*)d_in[19];
    float* out = (float*)d_out;

    k_convs    <<<NB*NF, 256>>>(inp,
                                fqkv_w, fqkv_g, fqkv_b, fqkv_m, fqkv_v, fqkv_a,
                                tqk_w,  tqk_g,  tqk_b,  tqk_m,  tqk_v,  tqk_a);
    k_transpose<<<dim3(NT/32, NF/32, NB*CF), dim3(32,8)>>>();
    k_cache_in <<<(2*NB*DC*NF*TCC)/256, 256>>>(cache);
    k_fattn    <<<NB*NT, 256>>>();
    k_escore   <<<NB*NF, 256>>>();
    k_lred     <<<NB*NY, 256>>>();
    k_tout     <<<NB*NF, 256>>>();
    k_proj     <<<NB*NF, 256>>>(inp, proj_w, proj_g, proj_b, proj_m, proj_v, proj_a, out);
    k_cache_out<<<(NB*2*DC*NF*(NY-1) + 255)/256, 256>>>(out);
}

// round 15
// speedup vs baseline: 1.0428x; 1.0428x over previous
#include <cuda_runtime.h>
#include <cuda_bf16.h>
#include <cstddef>

#define NB 4
#define CIN 64
#define NF 256
#define NT 256
#define TCC 64
#define DC 16
#define NY 320          // TCC + NT
#define CF 48           // 3*DC
#define CT 32           // 2*DC
#define CALL 80         // CF + CT
#define ATT_SCALE 0.25f // 1/sqrt(16)
#define ESHIFT 20.0f
#define EPS 1e-5f

// ---------------- packed fp32x2 helpers (sm_103a fma.rn.f32x2) --------------
typedef unsigned long long f32x2;
__device__ __forceinline__ f32x2 pk2(float lo, float hi) {
    f32x2 r; asm("mov.b64 %0,{%1,%2};" : "=l"(r) : "f"(lo), "f"(hi)); return r;
}
__device__ __forceinline__ void unpk2(f32x2 v, float& lo, float& hi) {
    asm("mov.b64 {%0,%1},%2;" : "=f"(lo), "=f"(hi) : "l"(v));
}
__device__ __forceinline__ void fma2(f32x2& d, f32x2 a, f32x2 b) {
    asm("fma.rn.f32x2 %0,%1,%2,%0;" : "+l"(d) : "l"(a), "l"(b));
}

// ---------------- scratch (__device__ globals; no runtime allocation) -------
__device__ float g_fqkv [NB*CF*NF*NT];        // [b][c48][f][t]
__device__ float g_fqkvT[NB*NT*CF*NF];        // [b][t][c48][f]
__device__ float g_qt   [NB*DC*NF*NT];        // [b][c][f][t]
__device__ float g_kt   [NB*DC*NF*NY];        // [b][c][f][y]  (y: cache|new)
__device__ float g_fout [NB*DC*NF*NY];        // [b][c][f][y]
__device__ __nv_bfloat16 g_E [(size_t)NB*NF*NY*NT]; // [b][f][y][t] bf16
__device__ float g_Lr   [NB*NY*NT];           // [b][y][t] = 1/L
__device__ float g_tout [NB*DC*NF*NT];        // [b][c][f][t]

// ---------------- fused conv 1x1 + BN + PReLU (fqkv 48ch + tqk 32ch) --------
__global__ void k_convs(const float* __restrict__ inp,
                        const float* __restrict__ wf,
                        const float* __restrict__ gf,
                        const float* __restrict__ bf_,
                        const float* __restrict__ mf,
                        const float* __restrict__ vf,
                        const float* __restrict__ af,
                        const float* __restrict__ wt,
                        const float* __restrict__ gt,
                        const float* __restrict__ bt_,
                        const float* __restrict__ mt,
                        const float* __restrict__ vt,
                        const float* __restrict__ at_)
{
    __shared__ float ws[CIN*CALL];     // 20KB: [c][j], j: 0..47 fqkv, 48..79 tqk
    __shared__ float sc[CALL], sh[CALL], al[CALL];
    int bf = blockIdx.x;
    int b = bf >> 8, f = bf & 255;
    int t = threadIdx.x;
    for (int i = t; i < CF*CIN; i += 256) {
        int j = i / CIN, c = i % CIN;
        ws[c*CALL + j] = wf[i];
    }
    for (int i = t; i < CT*CIN; i += 256) {
        int j = i / CIN, c = i % CIN;
        ws[c*CALL + CF + j] = wt[i];
    }
    if (t < CALL) {
        float gv, bv, mv, vv, av;
        if (t < CF) { gv=gf[t]; bv=bf_[t]; mv=mf[t]; vv=vf[t]; av=af[t]; }
        else { int j=t-CF; gv=gt[j]; bv=bt_[j]; mv=mt[j]; vv=vt[j]; av=at_[j]; }
        float r = rsqrtf(vv + EPS);
        sc[t] = gv * r;
        sh[t] = bv - mv * gv * r;
        al[t] = av;
    }
    __syncthreads();

    f32x2 acc[CALL/2];
    #pragma unroll
    for (int j = 0; j < CALL/2; j++) acc[j] = 0ULL;
    const float* ip = inp + ((size_t)b*CIN*NF + f)*NT + t;
    const ulonglong2* ws2 = (const ulonglong2*)ws;   // 20 per c-row
    for (int c = 0; c < CIN; c++) {
        float x = ip[(size_t)c*NF*NT];
        f32x2 xx = pk2(x, x);
        #pragma unroll
        for (int j4 = 0; j4 < CALL/4; j4++) {
            ulonglong2 w = ws2[c*(CALL/4) + j4];
            fma2(acc[2*j4+0], xx, w.x);
            fma2(acc[2*j4+1], xx, w.y);
        }
    }
    #pragma unroll
    for (int p = 0; p < CALL/2; p++) {
        float a0, a1;
        unpk2(acc[p], a0, a1);
        #pragma unroll
        for (int k = 0; k < 2; k++) {
            int j = 2*p + k;
            float av = (k == 0) ? a0 : a1;
            float yv = av*sc[j] + sh[j];
            yv = (yv >= 0.f) ? yv : al[j]*yv;
            if (j < CF)
                g_fqkv[(((size_t)b*CF + j)*NF + f)*NT + t] = yv;
            else if (j < CF + DC)
                g_qt[(((size_t)b*DC + (j-CF))*NF + f)*NT + t] = yv;
            else
                g_kt[(((size_t)b*DC + (j-CF-DC))*NF + f)*NY + TCC + t] = yv;
        }
    }
}

// ---------------- transpose [b][c][f][t] -> [b][t][c][f] --------------------
__global__ void k_transpose()
{
    __shared__ float tile[32][33];
    int bc = blockIdx.z;                 // b*CF + c
    int b = bc / CF, c = bc % CF;
    int f0 = blockIdx.y * 32, t0 = blockIdx.x * 32;
    const float* in = g_fqkv + (size_t)bc*NF*NT;
    for (int i = threadIdx.y; i < 32; i += 8)
        tile[i][threadIdx.x] = in[(size_t)(f0+i)*NT + t0 + threadIdx.x];
    __syncthreads();
    for (int i = threadIdx.y; i < 32; i += 8)
        g_fqkvT[(((size_t)b*NT + t0 + i)*CF + c)*NF + f0 + threadIdx.x]
            = tile[threadIdx.x][i];
}

// ---------------- splice cache into g_kt / g_fout ---------------------------
__global__ void k_cache_in(const float* __restrict__ cache)
{
    int idx = blockIdx.x*256 + threadIdx.x;
    int n = NB*DC*NF*TCC;
    int which = (idx >= n);          // 0: k_cache, 1: v_cache
    int i = which ? idx - n : idx;
    int tc = i % TCC;
    int f  = (i / TCC) % NF;
    int c  = (i / (TCC*NF)) % DC;
    int b  = i / (TCC*NF*DC);
    float val = cache[((((size_t)b*2*DC) + which*DC + c)*NF + f)*TCC + tc];
    float* dst = which ? g_fout : g_kt;
    dst[(((size_t)b*DC + c)*NF + f)*NY + tc] = val;
}

// ---------------- f-attention: per (b,t), softmax over y --------------------
// k,v staged in smem (32KB). q read coalesced from gmem. Packed f32x2 math.
__global__ void k_fattn()
{
    __shared__ float sm[CT*NF];   // k[0:16)|v[16:32), each [c][f] — 32KB
    int bt = blockIdx.x;
    int b = bt >> 8, t = bt & 255;
    const float* src = g_fqkvT + (size_t)(b*NT + t)*CF*NF;
    for (int i = threadIdx.x; i < CT*NF; i += 256) sm[i] = src[DC*NF + i];
    __syncthreads();

    int f = threadIdx.x;
    f32x2 qq[DC];
    #pragma unroll
    for (int c = 0; c < DC; c++) {
        float qv = src[c*NF + f];
        qq[c] = pk2(qv, qv);
    }
    f32x2 op[DC];   // packed over (even-y, odd-y) partial sums per c
    #pragma unroll
    for (int c = 0; c < DC; c++) op[c] = 0ULL;
    f32x2 lp = 0ULL;

    const ulonglong2* k2 = (const ulonglong2*)sm;            // [c][NF/4]
    const ulonglong2* v2 = (const ulonglong2*)(sm + DC*NF);
    for (int yg = 0; yg < NT/4; yg++) {
        f32x2 s01 = 0ULL, s23 = 0ULL;
        #pragma unroll
        for (int c = 0; c < DC; c++) {
            ulonglong2 kk = k2[c*(NF/4) + yg];
            fma2(s01, qq[c], kk.x);
            fma2(s23, qq[c], kk.y);
        }
        float s0, s1, s2, s3;
        unpk2(s01, s0, s1); unpk2(s23, s2, s3);
        float e0 = __expf(s0*ATT_SCALE - ESHIFT);
        float e1 = __expf(s1*ATT_SCALE - ESHIFT);
        float e2 = __expf(s2*ATT_SCALE - ESHIFT);
        float e3 = __expf(s3*ATT_SCALE - ESHIFT);
        f32x2 e01 = pk2(e0, e1), e23 = pk2(e2, e3);
        f32x2 one2 = pk2(1.f, 1.f);
        fma2(lp, e01, one2);
        fma2(lp, e23, one2);
        #pragma unroll
        for (int c = 0; c < DC; c++) {
            ulonglong2 vv = v2[c*(NF/4) + yg];
            fma2(op[c], e01, vv.x);
            fma2(op[c], e23, vv.y);
        }
    }
    float l0, l1;
    unpk2(lp, l0, l1);
    float inv = 1.f / (l0 + l1);
    #pragma unroll
    for (int c = 0; c < DC; c++) {
        float o0, o1;
        unpk2(op[c], o0, o1);
        g_fout[(((size_t)b*DC + c)*NF + f)*NY + TCC + t] = (o0 + o1)*inv;
    }
}

// ---------------- t-attention scores: E = exp(s*scale - C), bf16 ------------
__global__ void k_escore()
{
    __shared__ float qs[DC*NT];   // 16KB  [c][t]
    __shared__ float ks[DC*NY];   // 20KB  [c][y]
    int bf = blockIdx.x;
    int b = bf >> 8, f = bf & 255;
    for (int i = threadIdx.x; i < DC*NT; i += 256) {
        int c = i >> 8, t = i & 255;
        qs[i] = g_qt[(((size_t)b*DC + c)*NF + f)*NT + t];
    }
    for (int i = threadIdx.x; i < DC*NY; i += 256) {
        int c = i / NY, y = i - c*NY;
        ks[i] = g_kt[(((size_t)b*DC + c)*NF + f)*NY + y];
    }
    __syncthreads();

    int t = threadIdx.x;
    f32x2 qq[DC];
    #pragma unroll
    for (int c = 0; c < DC; c++) {
        float qv = qs[c*NT + t];
        qq[c] = pk2(qv, qv);
    }

    __nv_bfloat16* Eo = g_E + ((size_t)(b*NF + f)*NY)*NT + t;
    const ulonglong2* k2 = (const ulonglong2*)ks;    // [c][NY/4]
    for (int yg = 0; yg < NY/4; yg++) {
        f32x2 s01 = 0ULL, s23 = 0ULL;
        #pragma unroll
        for (int c = 0; c < DC; c++) {
            ulonglong2 kk = k2[c*(NY/4) + yg];
            fma2(s01, qq[c], kk.x);
            fma2(s23, qq[c], kk.y);
        }
        float s0, s1, s2, s3;
        unpk2(s01, s0, s1); unpk2(s23, s2, s3);
        Eo[(size_t)(4*yg+0)*NT] = __float2bfloat16(__expf(s0*ATT_SCALE - ESHIFT));
        Eo[(size_t)(4*yg+1)*NT] = __float2bfloat16(__expf(s1*ATT_SCALE - ESHIFT));
        Eo[(size_t)(4*yg+2)*NT] = __float2bfloat16(__expf(s2*ATT_SCALE - ESHIFT));
        Eo[(size_t)(4*yg+3)*NT] = __float2bfloat16(__expf(s3*ATT_SCALE - ESHIFT));
    }
}

// ---------------- reduce L over f, store reciprocal -------------------------
// 128 threads, each handles 2 t's via bf162 loads; f unrolled 8-deep (MLP=8).
__global__ void k_lred()
{
    int by = blockIdx.x;
    int b = by / NY, y = by % NY;
    int t2 = threadIdx.x;    // 0..127, covers t = 2*t2, 2*t2+1
    const __nv_bfloat162* e2 =
        (const __nv_bfloat162*)(g_E + ((size_t)b*NF*NY + y)*NT) + t2;
    const size_t st = (size_t)NY*NT/2;   // stride per f in bf162 units
    float lx = 0.f, ly = 0.f;
    for (int f = 0; f < NF; f += 8) {
        float2 v0 = __bfloat1622float2(e2[(size_t)(f+0)*st]);
        float2 v1 = __bfloat1622float2(e2[(size_t)(f+1)*st]);
        float2 v2 = __bfloat1622float2(e2[(size_t)(f+2)*st]);
        float2 v3 = __bfloat1622float2(e2[(size_t)(f+3)*st]);
        float2 v4 = __bfloat1622float2(e2[(size_t)(f+4)*st]);
        float2 v5 = __bfloat1622float2(e2[(size_t)(f+5)*st]);
        float2 v6 = __bfloat1622float2(e2[(size_t)(f+6)*st]);
        float2 v7 = __bfloat1622float2(e2[(size_t)(f+7)*st]);
        lx += ((v0.x + v1.x) + (v2.x + v3.x)) + ((v4.x + v5.x) + (v6.x + v7.x));
        ly += ((v0.y + v1.y) + (v2.y + v3.y)) + ((v4.y + v5.y) + (v6.y + v7.y));
    }
    float* Lr = g_Lr + ((size_t)b*NY + y)*NT;
    Lr[2*t2]   = 1.f / lx;
    Lr[2*t2+1] = 1.f / ly;
}

// ---------------- t_out = sum_y (E*Lr) * f_out ------------------------------
// fo smem layout [y][c]; packed f32x2 over c pairs.
__global__ void k_tout()
{
    __shared__ float fo[NY*DC];   // 20KB [y][c]
    int bf = blockIdx.x;
    int b = bf >> 8, f = bf & 255;
    for (int i = threadIdx.x; i < DC*NY; i += 256) {
        int c = i / NY, y = i - c*NY;
        fo[y*DC + c] = g_fout[(((size_t)b*DC + c)*NF + f)*NY + y];
    }
    __syncthreads();

    int t = threadIdx.x;
    f32x2 op[DC/2];
    #pragma unroll
    for (int p = 0; p < DC/2; p++) op[p] = 0ULL;
    const __nv_bfloat16* Ep = g_E  + (size_t)(b*NF + f)*NY*NT + t;
    const float* Lp = g_Lr + (size_t)b*NY*NT + t;
    const ulonglong2* fo2 = (const ulonglong2*)fo;   // 4 per y
    #pragma unroll 4
    for (int y = 0; y < NY; y++) {
        float p = __bfloat162float(Ep[(size_t)y*NT]) * Lp[(size_t)y*NT];
        f32x2 pp = pk2(p, p);
        #pragma unroll
        for (int c4 = 0; c4 < DC/4; c4++) {
            ulonglong2 vv = fo2[y*(DC/4) + c4];
            fma2(op[2*c4+0], pp, vv.x);
            fma2(op[2*c4+1], pp, vv.y);
        }
    }
    #pragma unroll
    for (int p = 0; p < DC/2; p++) {
        float o0, o1;
        unpk2(op[p], o0, o1);
        g_tout[(((size_t)b*DC + 2*p+0)*NF + f)*NT + t] = o0;
        g_tout[(((size_t)b*DC + 2*p+1)*NF + f)*NT + t] = o1;
    }
}

// ---------------- proj conv + BN + PReLU + residual -------------------------
__global__ void k_proj(const float* __restrict__ inp,
                       const float* __restrict__ w,
                       const float* __restrict__ g,
                       const float* __restrict__ bb,
                       const float* __restrict__ m,
                       const float* __restrict__ v,
                       const float* __restrict__ a,
                       float* __restrict__ out)
{
    __shared__ float ws[DC*CIN];   // [c][oc]
    __shared__ float sc[CIN], sh[CIN], al[CIN];
    int bf = blockIdx.x;
    int b = bf >> 8, f = bf & 255;
    int t = threadIdx.x;
    for (int i = t; i < CIN*DC; i += 256) {
        int oc = i / DC, c = i % DC;
        ws[c*CIN + oc] = w[i];
    }
    if (t < CIN) {
        float r = rsqrtf(v[t] + EPS);
        sc[t] = g[t] * r;
        sh[t] = bb[t] - m[t] * g[t] * r;
        al[t] = a[t];
    }
    __syncthreads();

    f32x2 acc[CIN/2];
    #pragma unroll
    for (int p = 0; p < CIN/2; p++) acc[p] = 0ULL;
    const ulonglong2* ws2 = (const ulonglong2*)ws;   // 16 per c-row
    #pragma unroll
    for (int c = 0; c < DC; c++) {
        float x = g_tout[(((size_t)b*DC + c)*NF + f)*NT + t];
        f32x2 xx = pk2(x, x);
        #pragma unroll
        for (int o4 = 0; o4 < CIN/4; o4++) {
            ulonglong2 wv = ws2[c*(CIN/4) + o4];
            fma2(acc[2*o4+0], xx, wv.x);
            fma2(acc[2*o4+1], xx, wv.y);
        }
    }
    #pragma unroll
    for (int p = 0; p < CIN/2; p++) {
        float a0, a1;
        unpk2(acc[p], a0, a1);
        #pragma unroll
        for (int k = 0; k < 2; k++) {
            int oc = 2*p + k;
            float av = (k == 0) ? a0 : a1;
            float yv = av*sc[oc] + sh[oc];
            yv = (yv >= 0.f) ? yv : al[oc]*yv;
            size_t idx = (((size_t)b*CIN + oc)*NF + f)*NT + t;
            out[idx] = yv + inp[idx];
        }
    }
}

// ---------------- write new_cache slice -------------------------------------
__global__ void k_cache_out(float* __restrict__ out)
{
    int idx = blockIdx.x*256 + threadIdx.x;
    const int n = NB * 2*DC * NF * (NY-1);  // 10,452,992
    if (idx >= n) return;
    int i = idx;
    int yy = i % (NY-1); i /= (NY-1);
    int f  = i % NF;     i /= NF;
    int cc = i % (2*DC); i /= (2*DC);
    int b  = i;
    const float* src = (cc < DC) ? g_kt : g_fout;
    int c = (cc < DC) ? cc : cc - DC;
    out[(size_t)NB*CIN*NF*NT + idx] =
        src[(((size_t)b*DC + c)*NF + f)*NY + 1 + yy];
}

// ---------------- launcher --------------------------------------------------
extern "C" void kernel_launch(void* const* d_in, const int* in_sizes, int n_in,
                              void* d_out, int out_size)
{
    const float* inp    = (const float*)d_in[0];
    const float* cache  = (const float*)d_in[1];
    const float* fqkv_w = (const float*)d_in[2];
    const float* fqkv_g = (const float*)d_in[3];
    const float* fqkv_b = (const float*)d_in[4];
    const float* fqkv_m = (const float*)d_in[5];
    const float* fqkv_v = (const float*)d_in[6];
    const float* fqkv_a = (const float*)d_in[7];
    const float* tqk_w  = (const float*)d_in[8];
    const float* tqk_g  = (const float*)d_in[9];
    const float* tqk_b  = (const float*)d_in[10];
    const float* tqk_m  = (const float*)d_in[11];
    const float* tqk_v  = (const float*)d_in[12];
    const float* tqk_a  = (const float*)d_in[13];
    const float* proj_w = (const float*)d_in[14];
    const float* proj_g = (const float*)d_in[15];
    const float* proj_b = (const float*)d_in[16];
    const float* proj_m = (const float*)d_in[17];
    const float* proj_v = (const float*)d_in[18];
    const float* proj_a = (const float*)d_in[19];
    float* out = (float*)d_out;

    k_convs    <<<NB*NF, 256>>>(inp,
                                fqkv_w, fqkv_g, fqkv_b, fqkv_m, fqkv_v, fqkv_a,
                                tqk_w,  tqk_g,  tqk_b,  tqk_m,  tqk_v,  tqk_a);
    k_transpose<<<dim3(NT/32, NF/32, NB*CF), dim3(32,8)>>>();
    k_cache_in <<<(2*NB*DC*NF*TCC)/256, 256>>>(cache);
    k_fattn    <<<NB*NT, 256>>>();
    k_escore   <<<NB*NF, 256>>>();
    k_lred     <<<NB*NY, 128>>>();
    k_tout     <<<NB*NF, 256>>>();
    k_proj     <<<NB*NF, 256>>>(inp, proj_w, proj_g, proj_b, proj_m, proj_v, proj_a, out);
    k_cache_out<<<(NB*2*DC*NF*(NY-1) + 255)/256, 256>>>(out);
}